// round 15
// baseline (speedup 1.0000x reference)
#include <cuda_runtime.h>
#include <cuda_fp16.h>
#include <math.h>
#include <stdint.h>

#define CO   256
#define HW   128
#define NB   16

// ---------------- device scratch ----------------
__device__ __align__(16) __half g_yh[(size_t)NB * HW * HW * CO];      // layer-1 out NHWC fp16
__device__ __align__(16) __half g_xh[(size_t)NB * HW * HW * 128];     // x NHWC fp16
__device__ float  g_bank1[4 * 256 * 128 * 9];                          // [kb][co][tap][ci]
__device__ float  g_bank2[4 * 256 * 256 * 9];
__device__ __align__(16) __half g_wmix1[(size_t)NB * CO * 128 * 9];    // [b][co][tap*CIN+ci]
__device__ __align__(16) __half g_wmix2[(size_t)NB * CO * 256 * 9];
__device__ float  g_gpart[(size_t)NB * 128 * 128];                     // [b][gy][ci] partials
__device__ float  g_gap2[NB * 256];
__device__ float  g_attn[NB * 4];

// ---------------- PTX helpers (base sm_103-safe only) ----------------
__device__ __forceinline__ uint32_t smem_u32(const void* p) {
    uint32_t a;
    asm("{ .reg .u64 t; cvta.to.shared.u64 t, %1; cvt.u32.u64 %0, t; }" : "=r"(a) : "l"(p));
    return a;
}
__device__ __forceinline__ void ldsm_x4(uint32_t& r0, uint32_t& r1, uint32_t& r2, uint32_t& r3,
                                        uint32_t addr) {
    asm volatile("ldmatrix.sync.aligned.m8n8.x4.shared.b16 {%0,%1,%2,%3}, [%4];"
                 : "=r"(r0), "=r"(r1), "=r"(r2), "=r"(r3) : "r"(addr));
}
__device__ __forceinline__ void mma16816(float* d, const uint32_t* a, uint32_t b0, uint32_t b1) {
    asm volatile("mma.sync.aligned.m16n8k16.row.col.f32.f16.f16.f32 "
                 "{%0,%1,%2,%3}, {%4,%5,%6,%7}, {%8,%9}, {%0,%1,%2,%3};"
                 : "+f"(d[0]), "+f"(d[1]), "+f"(d[2]), "+f"(d[3])
                 : "r"(a[0]), "r"(a[1]), "r"(a[2]), "r"(a[3]), "r"(b0), "r"(b1));
}
__device__ __forceinline__ void cp_async16(uint32_t dst, const void* src) {
    asm volatile("cp.async.ca.shared.global [%0], [%1], 16;" :: "r"(dst), "l"(src) : "memory");
}
#define CP_COMMIT()  asm volatile("cp.async.commit_group;" ::: "memory")
#define CP_WAIT(n)   asm volatile("cp.async.wait_group %0;" :: "n"(n) : "memory")

// ---------------- irfft2 synthesis (device body) ----------------
__device__ __forceinline__ void synth_body(const float* __restrict__ fr,
                                           const float* __restrict__ fi,
                                           float* __restrict__ bank, int Ci, int idx) {
    int ci = idx % Ci;
    int t  = idx / Ci;   // kb*CO + co
    const float* pr = fr + (size_t)idx * 6;
    const float* pi = fi + (size_t)idx * 6;
    float Fr[3][2], Fi[3][2];
#pragma unroll
    for (int a = 0; a < 3; a++)
#pragma unroll
        for (int x2 = 0; x2 < 2; x2++) {
            Fr[a][x2] = pr[a * 2 + x2];
            Fi[a][x2] = pi[a * 2 + x2];
        }
    const float Hs = 0.86602540378443864676f;
    const float cm[3] = { 1.f, -0.5f, -0.5f };
    const float sm[3] = { 0.f,  Hs,   -Hs  };
    float* outp = bank + ((size_t)t * 9) * Ci + ci;
#pragma unroll
    for (int y = 0; y < 3; y++) {
        float Gr0 = 0.f, Gr1 = 0.f, Gi1 = 0.f;
#pragma unroll
        for (int ky = 0; ky < 3; ky++) {
            int m = (ky * y) % 3;
            float c = cm[m], s = sm[m];
            Gr0 += Fr[ky][0] * c - Fi[ky][0] * s;
            Gr1 += Fr[ky][1] * c - Fi[ky][1] * s;
            Gi1 += Fr[ky][1] * s + Fi[ky][1] * c;
        }
#pragma unroll
        for (int xx = 0; xx < 3; xx++)
            outp[(size_t)(y * 3 + xx) * Ci] = (Gr0 + 2.f * (Gr1 * cm[xx] - Gi1 * sm[xx])) * (1.f / 9.f);
    }
}

// ---------------- prep: NCHW->NHWC fp16 + GAP partials | zero gap2 | synth ----------------
__global__ void prep_kernel(const float* __restrict__ x, __half* __restrict__ xh,
                            float* __restrict__ gpart, float* __restrict__ gap2,
                            const float* __restrict__ w1fr, const float* __restrict__ w1fi,
                            float* __restrict__ bank1,
                            const float* __restrict__ w2fr, const float* __restrict__ w2fi,
                            float* __restrict__ bank2) {
    const int bid = blockIdx.x;
    if (bid < 2048) {
        __shared__ __half sm[128 * 130];
        const int b = bid >> 7, gy = bid & 127;
        const int w = threadIdx.x >> 5, l = threadIdx.x & 31;
#pragma unroll 4
        for (int rep = 0; rep < 16; rep++) {
            int ci = w * 16 + rep;
            float4 v = __ldg(reinterpret_cast<const float4*>(
                x + ((size_t)(b * 128 + ci) * HW + gy) * HW) + l);
            float s = (v.x + v.y) + (v.z + v.w);
            for (int o = 16; o; o >>= 1) s += __shfl_down_sync(0xffffffffu, s, o);
            if (l == 0) gpart[((size_t)b * 128 + gy) * 128 + ci] = s;
            __half2 h0 = __floats2half2_rn(v.x, v.y);
            __half2 h1 = __floats2half2_rn(v.z, v.w);
            *reinterpret_cast<__half2*>(&sm[ci * 130 + l * 4])     = h0;
            *reinterpret_cast<__half2*>(&sm[ci * 130 + l * 4 + 2]) = h1;
        }
        __syncthreads();
        const int gx = threadIdx.x >> 1, part = threadIdx.x & 1;
        __half* dst = xh + ((size_t)(b * 128 + gy) * 128 + gx) * 128 + part * 64;
#pragma unroll
        for (int c8 = 0; c8 < 8; c8++) {
            __half h[8];
#pragma unroll
            for (int j = 0; j < 8; j++) h[j] = sm[(part * 64 + c8 * 8 + j) * 130 + gx];
            __half2 p0 = __halves2half2(h[0], h[1]);
            __half2 p1 = __halves2half2(h[2], h[3]);
            __half2 p2 = __halves2half2(h[4], h[5]);
            __half2 p3 = __halves2half2(h[6], h[7]);
            uint4 u;
            u.x = *reinterpret_cast<uint32_t*>(&p0);
            u.y = *reinterpret_cast<uint32_t*>(&p1);
            u.z = *reinterpret_cast<uint32_t*>(&p2);
            u.w = *reinterpret_cast<uint32_t*>(&p3);
            *reinterpret_cast<uint4*>(dst + c8 * 8) = u;
        }
    } else if (bid < 2064) {
        int i = (bid - 2048) * 256 + threadIdx.x;
        if (i < NB * 256) gap2[i] = 0.f;
    } else if (bid < 2576) {
        int idx = (bid - 2064) * 256 + threadIdx.x;
        if (idx < 4 * CO * 128) synth_body(w1fr, w1fi, bank1, 128, idx);
    } else {
        int idx = (bid - 2576) * 256 + threadIdx.x;
        if (idx < 4 * CO * 256) synth_body(w2fr, w2fi, bank2, 256, idx);
    }
}

// ---------------- GAP -> MLP -> softmax (parts: reduce per-gy partials) ----------------
__global__ void attn_kernel(const float* __restrict__ gap, const float* __restrict__ w1,
                            const float* __restrict__ b1, const float* __restrict__ w2,
                            const float* __restrict__ b2, float* __restrict__ attn,
                            int C, int Hd, int parts) {
    __shared__ float gs[256];
    __shared__ float hbuf[64];
    int b = blockIdx.x;
    if (parts) {
        for (int i = threadIdx.x; i < C; i += blockDim.x) {
            float s = 0.f;
            const float* p = gap + (size_t)b * 128 * 128 + i;
            for (int gy = 0; gy < 128; gy++) s += p[gy * 128];
            gs[i] = s * (1.f / (HW * HW));
        }
    } else {
        for (int i = threadIdx.x; i < C; i += blockDim.x) gs[i] = gap[b * C + i];
    }
    __syncthreads();
    for (int j = threadIdx.x; j < Hd; j += blockDim.x) {
        float s = b1[j];
        for (int c = 0; c < C; c++) s += gs[c] * w1[c * Hd + j];
        hbuf[j] = fmaxf(s, 0.f);
    }
    __syncthreads();
    if (threadIdx.x == 0) {
        float l[4];
        float m = -1e30f;
        for (int k = 0; k < 4; k++) {
            float s = b2[k];
            for (int j = 0; j < Hd; j++) s += hbuf[j] * w2[j * 4 + k];
            l[k] = s; m = fmaxf(m, s);
        }
        float sum = 0.f;
        for (int k = 0; k < 4; k++) { l[k] = expf(l[k] - m); sum += l[k]; }
        float inv = 1.f / sum;
        for (int k = 0; k < 4; k++) attn[b * 4 + k] = l[k] * inv;
    }
}

// ---------------- weight mix ----------------
__global__ void mix_kernel(const float* __restrict__ bank, const float* __restrict__ attn,
                           __half* __restrict__ wmix, int K) {
    int total = NB * CO * (K / 2);
    int i = blockIdx.x * blockDim.x + threadIdx.x;
    if (i >= total) return;
    int perb = CO * (K / 2);
    int b = i / perb;
    int r = (i - b * perb) * 2;           // co*K + k  (tap-major k)
    float a0 = attn[b * 4 + 0], a1 = attn[b * 4 + 1];
    float a2 = attn[b * 4 + 2], a3 = attn[b * 4 + 3];
    int plane = CO * K;
    const float* p = bank + r;
    float x0 = a0 * p[0] + a1 * p[plane] + a2 * p[2 * plane] + a3 * p[3 * plane];
    float x1 = a0 * p[1] + a1 * p[plane + 1] + a2 * p[2 * plane + 1] + a3 * p[3 * plane + 1];
    reinterpret_cast<__half2*>(wmix)[i] = __floats2half2_rn(x0, x1);
}

// ---------------- HMMA implicit-GEMM conv (persistent NHWC im2col plane) ----------------
// CTA = (b, 128-co half, 2 rows = 256 px). 512 thr, 16 warps 4x4 (32co x 64px tiles).
// B: per-64ci group, one smem plane [4 gy][130 gx][64 ci] (rows 144B) serves all 9 taps;
// (dy,dx) shift = row-pointer offset, non-trans ldmatrix (px-major B). Double-buffered.
// A: wmix chunks quad-buffered via cp.async. ONE barrier per 2 chunks; all cp.async
// issued at pair start so the pair-end wait_group(0) never stalls.
#define SA    72                  // halves per A row (144B)
#define ABYTES (128 * SA * 2)     // 18432
#define BROW  144                 // bytes per B plane row (64 ci + pad)
#define SBP   (520 * BROW)        // 74880 bytes per plane (4*130 rows)
#define SBOFF (4 * ABYTES)        // 73728
#define SMTOT (SBOFF + 2 * SBP)   // 223488

template<int CIN, bool OUT_HALF, bool GAP_OUT>
__global__ void __launch_bounds__(512, 1)
conv_hmma_kernel(const __half* __restrict__ xh, const __half* __restrict__ wmix,
                 const float* __restrict__ bias, void* __restrict__ outv,
                 float* __restrict__ gapout) {
    constexpr int K    = CIN * 9;
    constexpr int NCIG = CIN / 64;
    constexpr int NCH  = 9 * NCIG;

    extern __shared__ __align__(16) char smem[];
    const uint32_t sbase = smem_u32(smem);
    const uint32_t sbB   = sbase + SBOFF;

    const int tid = threadIdx.x, wid = tid >> 5, lane = tid & 31;
    const int b   = blockIdx.z;
    const int co0 = blockIdx.y * 128;
    const int y0  = blockIdx.x * 2;
    const int wr = wid & 3, wc = wid >> 2;

    const __half* xb = xh + (size_t)b * HW * HW * CIN;     // NHWC
    const __half* wb = wmix + (size_t)(b * 256 + co0) * K;

    float d[2][8][4];
#pragma unroll
    for (int mt = 0; mt < 2; mt++)
#pragma unroll
        for (int nt = 0; nt < 8; nt++)
#pragma unroll
            for (int q = 0; q < 4; q++) d[mt][nt][q] = 0.f;

    // A cp.async mapping: thread -> rows (tid>>3, +64), seg tid&7
    const int arow = tid >> 3, aseg = tid & 7;
    const __half* asrc0 = wb + (size_t)arow * K + aseg * 8;
    const uint32_t adst0 = sbase + (uint32_t)(arow * SA + aseg * 8) * 2;

    auto cpa_a = [&](int cc) {
        int tap = cc % 9, cig = cc / 9;
        const __half* asrc = asrc0 + tap * CIN + cig * 64;
        const uint32_t adst = adst0 + (cc & 3) * ABYTES;
        cp_async16(adst, asrc);
        cp_async16(adst + 64 * SA * 2, asrc + (size_t)64 * K);
    };

    // fill B plane for ci-group cig into buffer (cig&1): 4096 tasks (4gy x 128gx x 8seg)
    auto fill_b = [&](int cig) {
        const uint32_t pl = sbB + (cig & 1) * SBP;
#pragma unroll
        for (int i = 0; i < 8; i++) {
            int task = tid + i * 512;
            int gy = task >> 10, rem = task & 1023, gx = rem >> 3, seg = rem & 7;
            int gyg = y0 + gy - 1;
            if ((unsigned)gyg < 128u) {
                uint32_t dst = pl + (uint32_t)((gy * 130 + gx + 1) * BROW + seg * 16);
                const __half* src = xb + ((size_t)gyg * HW + gx) * CIN + cig * 64 + seg * 8;
                cp_async16(dst, src);
            }
        }
    };

    // one chunk's compute: 4 k16-steps against A buf (c&3) and B plane (cig&1)
    auto chunk_compute = [&](int c) {
        const int tap = c % 9, cig = c / 9;
        const int dy = tap / 3, dx = tap % 3;
        const uint32_t sa = sbase + (c & 3) * ABYTES;
        const uint32_t bplane = sbB + (cig & 1) * SBP;

        uint32_t brow[4];
#pragma unroll
        for (int ng = 0; ng < 4; ng++) {
            int n_g = wc * 64 + ng * 16 + (lane & 7) + ((lane >> 4) << 3);
            int yr = n_g >> 7, gx = n_g & 127;
            brow[ng] = bplane + (uint32_t)(((yr + dy) * 130 + gx + dx) * BROW
                                           + ((lane >> 3) & 1) * 16);
        }

#pragma unroll
        for (int ks = 0; ks < 4; ks++) {
            uint32_t a[2][4];
#pragma unroll
            for (int mt = 0; mt < 2; mt++) {
                uint32_t addr = sa + (uint32_t)((wr * 32 + mt * 16 + (lane & 15)) * SA
                                                + ks * 16 + (lane >> 4) * 8) * 2;
                ldsm_x4(a[mt][0], a[mt][1], a[mt][2], a[mt][3], addr);
            }
            uint32_t bf[2][4];
            ldsm_x4(bf[0][0], bf[0][1], bf[0][2], bf[0][3], brow[0] + ks * 32);
#pragma unroll
            for (int ng = 0; ng < 4; ng++) {
                if (ng < 3)
                    ldsm_x4(bf[(ng + 1) & 1][0], bf[(ng + 1) & 1][1],
                            bf[(ng + 1) & 1][2], bf[(ng + 1) & 1][3],
                            brow[ng + 1] + ks * 32);
                const uint32_t* f = bf[ng & 1];
#pragma unroll
                for (int mt = 0; mt < 2; mt++) {
                    mma16816(d[mt][ng * 2 + 0], a[mt], f[0], f[1]);
                    mma16816(d[mt][ng * 2 + 1], a[mt], f[2], f[3]);
                }
            }
        }
    };

    // ---- zero halo / OOB rows of both planes ----
    for (int i = tid; i < 2 * 8 * 36; i += 512) {
        int pl = i / 288, r8 = (i / 36) % 8, u = i % 36;
        int gy = r8 >> 1;
        int row = gy * 130 + ((r8 & 1) ? 129 : 0);
        *reinterpret_cast<uint32_t*>(smem + SBOFF + pl * SBP + row * BROW + u * 4) = 0u;
    }
    if (y0 == 0) {
        for (int i = tid; i < 2 * 130 * 36; i += 512) {
            int pl = i / (130 * 36), r = (i / 36) % 130, u = i % 36;
            *reinterpret_cast<uint32_t*>(smem + SBOFF + pl * SBP + r * BROW + u * 4) = 0u;
        }
    }
    if (y0 == 126) {
        for (int i = tid; i < 2 * 130 * 36; i += 512) {
            int pl = i / (130 * 36), r = (i / 36) % 130 + 390, u = i % 36;
            *reinterpret_cast<uint32_t*>(smem + SBOFF + pl * SBP + r * BROW + u * 4) = 0u;
        }
    }
    __syncthreads();

    // ---- prologue: first plane + first two A chunks ----
    fill_b(0);
    cpa_a(0);
    cpa_a(1);
    CP_COMMIT();
    CP_WAIT(0);
    __syncthreads();

    // ---- pair loop: barrier every 2 chunks ----
    for (int q = 0; q < NCH / 2; q++) {
        const int c0 = 2 * q;
        // pair-start prefetch (after barrier: all prior reads of target bufs done)
        if (c0 + 2 < NCH) cpa_a(c0 + 2);
        if (c0 + 3 < NCH) cpa_a(c0 + 3);
        {
            int r = c0 % 9;
            if (r == 1 || r == 2) {
                int nc = c0 / 9 + 1;
                if (nc < NCIG) fill_b(nc);
            }
        }
        CP_COMMIT();

        chunk_compute(c0);
        chunk_compute(c0 + 1);

        CP_WAIT(0);            // groups had a full pair of compute to land — no stall
        __syncthreads();
    }

    // ---- epilogue ----
    if (GAP_OUT) {
#pragma unroll
        for (int mt = 0; mt < 2; mt++) {
#pragma unroll
            for (int h = 0; h < 2; h++) {
                int co = co0 + wr * 32 + mt * 16 + (lane >> 2) + h * 8;
                float bv = bias[co];
                float gs = 0.f;
#pragma unroll
                for (int nt = 0; nt < 8; nt++) {
                    gs += fmaxf(d[mt][nt][h * 2 + 0] + bv, 0.f)
                        + fmaxf(d[mt][nt][h * 2 + 1] + bv, 0.f);
                }
                gs += __shfl_xor_sync(0xffffffffu, gs, 1);
                gs += __shfl_xor_sync(0xffffffffu, gs, 2);
                if ((lane & 3) == 0)
                    atomicAdd(&gapout[b * 256 + co], gs * (1.f / (HW * HW)));
            }
        }
    }

    if (OUT_HALF) {
        // stage [px 256][co 136] fp16 in B smem area, then coalesced NHWC writes
        __half* st = reinterpret_cast<__half*>(smem + SBOFF);
#pragma unroll
        for (int mt = 0; mt < 2; mt++) {
#pragma unroll
            for (int h = 0; h < 2; h++) {
                int col = wr * 32 + mt * 16 + (lane >> 2) + h * 8;
                float bv = bias[co0 + col];
#pragma unroll
                for (int nt = 0; nt < 8; nt++) {
                    int px = wc * 64 + nt * 8 + (lane & 3) * 2;
                    st[px * 136 + col]       = __float2half(fmaxf(d[mt][nt][h * 2 + 0] + bv, 0.f));
                    st[(px + 1) * 136 + col] = __float2half(fmaxf(d[mt][nt][h * 2 + 1] + bv, 0.f));
                }
            }
        }
        __syncthreads();
        const int px = tid >> 1, part = tid & 1;
        int gyO = y0 + (px >> 7), gx = px & 127;
        __half* dst = (__half*)outv + ((size_t)(b * 128 + gyO) * 128 + gx) * 256 + co0 + part * 64;
#pragma unroll
        for (int c8 = 0; c8 < 8; c8++) {
            __half h[8];
#pragma unroll
            for (int j = 0; j < 8; j++) h[j] = st[px * 136 + part * 64 + c8 * 8 + j];
            __half2 p0 = __halves2half2(h[0], h[1]);
            __half2 p1 = __halves2half2(h[2], h[3]);
            __half2 p2 = __halves2half2(h[4], h[5]);
            __half2 p3 = __halves2half2(h[6], h[7]);
            uint4 u;
            u.x = *reinterpret_cast<uint32_t*>(&p0);
            u.y = *reinterpret_cast<uint32_t*>(&p1);
            u.z = *reinterpret_cast<uint32_t*>(&p2);
            u.w = *reinterpret_cast<uint32_t*>(&p3);
            *reinterpret_cast<uint4*>(dst + c8 * 8) = u;
        }
    } else {
        // NCHW fp32 direct stores (final output)
#pragma unroll
        for (int mt = 0; mt < 2; mt++) {
#pragma unroll
            for (int h = 0; h < 2; h++) {
                int co = co0 + wr * 32 + mt * 16 + (lane >> 2) + h * 8;
                float bv = bias[co];
                size_t base = ((size_t)(b * 256 + co) * HW + y0) * HW;
#pragma unroll
                for (int nt = 0; nt < 8; nt++) {
                    int px = wc * 64 + nt * 8 + (lane & 3) * 2;
                    int yr = px >> 7, xx = px & 127;
                    float2 fv;
                    fv.x = fmaxf(d[mt][nt][h * 2 + 0] + bv, 0.f);
                    fv.y = fmaxf(d[mt][nt][h * 2 + 1] + bv, 0.f);
                    *reinterpret_cast<float2*>((float*)outv + base + yr * HW + xx) = fv;
                }
            }
        }
    }
}

// ---------------- launch ----------------
extern "C" void kernel_launch(void* const* d_in, const int* in_sizes, int n_in,
                              void* d_out, int out_size) {
    const float* x    = (const float*)d_in[0];
    const float* w1fr = (const float*)d_in[1];
    const float* w1fi = (const float*)d_in[2];
    const float* b1   = (const float*)d_in[3];
    const float* a1w1 = (const float*)d_in[4];
    const float* a1b1 = (const float*)d_in[5];
    const float* a1w2 = (const float*)d_in[6];
    const float* a1b2 = (const float*)d_in[7];
    const float* w2fr = (const float*)d_in[8];
    const float* w2fi = (const float*)d_in[9];
    const float* b2   = (const float*)d_in[10];
    const float* a2w1 = (const float*)d_in[11];
    const float* a2b1 = (const float*)d_in[12];
    const float* a2w2 = (const float*)d_in[13];
    const float* a2b2 = (const float*)d_in[14];
    float* out = (float*)d_out;

    float *bank1, *bank2, *gpart, *gap2, *attnb;
    __half *wm1, *wm2, *xhb, *yhb;
    cudaGetSymbolAddress((void**)&bank1, g_bank1);
    cudaGetSymbolAddress((void**)&bank2, g_bank2);
    cudaGetSymbolAddress((void**)&gpart, g_gpart);
    cudaGetSymbolAddress((void**)&gap2,  g_gap2);
    cudaGetSymbolAddress((void**)&attnb, g_attn);
    cudaGetSymbolAddress((void**)&wm1,   g_wmix1);
    cudaGetSymbolAddress((void**)&wm2,   g_wmix2);
    cudaGetSymbolAddress((void**)&xhb,   g_xh);
    cudaGetSymbolAddress((void**)&yhb,   g_yh);

    cudaFuncSetAttribute(conv_hmma_kernel<128, true, true>,
                         cudaFuncAttributeMaxDynamicSharedMemorySize, SMTOT);
    cudaFuncSetAttribute(conv_hmma_kernel<256, false, false>,
                         cudaFuncAttributeMaxDynamicSharedMemorySize, SMTOT);

    // Launch order: conv1 is launch index 3 (the one ncu captures).
    prep_kernel<<<3600, 256>>>(x, xhb, gpart, gap2,
                               w1fr, w1fi, bank1, w2fr, w2fi, bank2);                 // 0
    attn_kernel<<<NB, 128>>>(gpart, a1w1, a1b1, a1w2, a1b2, attnb, 128, 32, 1);       // 1
    {
        int K = 128 * 9;
        int total = NB * CO * (K / 2);
        mix_kernel<<<(total + 255) / 256, 256>>>(bank1, attnb, wm1, K);               // 2
    }
    conv_hmma_kernel<128, true, true><<<dim3(64, 2, NB), 512, SMTOT>>>(xhb, wm1, b1, yhb, gap2);  // 3

    attn_kernel<<<NB, 128>>>(gap2, a2w1, a2b1, a2w2, a2b2, attnb, 256, 64, 0);        // 4
    {
        int K = 256 * 9;
        int total = NB * CO * (K / 2);
        mix_kernel<<<(total + 255) / 256, 256>>>(bank2, attnb, wm2, K);               // 5
    }
    conv_hmma_kernel<256, false, false><<<dim3(64, 2, NB), 512, SMTOT>>>(yhb, wm2, b2, out, nullptr);  // 6
}

// round 16
// speedup vs baseline: 1.0981x; 1.0981x over previous
#include <cuda_runtime.h>
#include <cuda_fp16.h>
#include <math.h>
#include <stdint.h>

#define CO   256
#define HW   128
#define NB   16

// ---------------- device scratch ----------------
__device__ __align__(16) __half g_yh[(size_t)NB * HW * HW * CO];      // layer-1 out NHWC fp16
__device__ __align__(16) __half g_xh[(size_t)NB * HW * HW * 128];     // x NHWC fp16
__device__ float  g_bank1[4 * 256 * 128 * 9];                          // [kb][co][tap][ci]
__device__ float  g_bank2[4 * 256 * 256 * 9];
__device__ __align__(16) __half g_wmix1[(size_t)NB * CO * 128 * 9];    // [b][co][tap*CIN+ci]
__device__ __align__(16) __half g_wmix2[(size_t)NB * CO * 256 * 9];
__device__ float  g_gpart[(size_t)NB * 128 * 128];                     // [b][gy][ci] partials
__device__ float  g_gap2[NB * 256];
__device__ float  g_attn[NB * 4];

// ---------------- PTX helpers (base sm_103-safe only) ----------------
__device__ __forceinline__ uint32_t smem_u32(const void* p) {
    uint32_t a;
    asm("{ .reg .u64 t; cvta.to.shared.u64 t, %1; cvt.u32.u64 %0, t; }" : "=r"(a) : "l"(p));
    return a;
}
__device__ __forceinline__ void ldsm_x4(uint32_t& r0, uint32_t& r1, uint32_t& r2, uint32_t& r3,
                                        uint32_t addr) {
    asm volatile("ldmatrix.sync.aligned.m8n8.x4.shared.b16 {%0,%1,%2,%3}, [%4];"
                 : "=r"(r0), "=r"(r1), "=r"(r2), "=r"(r3) : "r"(addr));
}
__device__ __forceinline__ void mma16816(float* d, const uint32_t* a, uint32_t b0, uint32_t b1) {
    asm volatile("mma.sync.aligned.m16n8k16.row.col.f32.f16.f16.f32 "
                 "{%0,%1,%2,%3}, {%4,%5,%6,%7}, {%8,%9}, {%0,%1,%2,%3};"
                 : "+f"(d[0]), "+f"(d[1]), "+f"(d[2]), "+f"(d[3])
                 : "r"(a[0]), "r"(a[1]), "r"(a[2]), "r"(a[3]), "r"(b0), "r"(b1));
}
__device__ __forceinline__ void cp_async16(uint32_t dst, const void* src) {
    asm volatile("cp.async.ca.shared.global [%0], [%1], 16;" :: "r"(dst), "l"(src) : "memory");
}
#define CP_COMMIT()  asm volatile("cp.async.commit_group;" ::: "memory")
#define CP_WAIT(n)   asm volatile("cp.async.wait_group %0;" :: "n"(n) : "memory")

// ---------------- irfft2 synthesis (device body) ----------------
__device__ __forceinline__ void synth_body(const float* __restrict__ fr,
                                           const float* __restrict__ fi,
                                           float* __restrict__ bank, int Ci, int idx) {
    int ci = idx % Ci;
    int t  = idx / Ci;   // kb*CO + co
    const float* pr = fr + (size_t)idx * 6;
    const float* pi = fi + (size_t)idx * 6;
    float Fr[3][2], Fi[3][2];
#pragma unroll
    for (int a = 0; a < 3; a++)
#pragma unroll
        for (int x2 = 0; x2 < 2; x2++) {
            Fr[a][x2] = pr[a * 2 + x2];
            Fi[a][x2] = pi[a * 2 + x2];
        }
    const float Hs = 0.86602540378443864676f;
    const float cm[3] = { 1.f, -0.5f, -0.5f };
    const float sm[3] = { 0.f,  Hs,   -Hs  };
    float* outp = bank + ((size_t)t * 9) * Ci + ci;
#pragma unroll
    for (int y = 0; y < 3; y++) {
        float Gr0 = 0.f, Gr1 = 0.f, Gi1 = 0.f;
#pragma unroll
        for (int ky = 0; ky < 3; ky++) {
            int m = (ky * y) % 3;
            float c = cm[m], s = sm[m];
            Gr0 += Fr[ky][0] * c - Fi[ky][0] * s;
            Gr1 += Fr[ky][1] * c - Fi[ky][1] * s;
            Gi1 += Fr[ky][1] * s + Fi[ky][1] * c;
        }
#pragma unroll
        for (int xx = 0; xx < 3; xx++)
            outp[(size_t)(y * 3 + xx) * Ci] = (Gr0 + 2.f * (Gr1 * cm[xx] - Gi1 * sm[xx])) * (1.f / 9.f);
    }
}

// ---------------- prep: NCHW->NHWC fp16 + GAP partials | zero gap2 | synth ----------------
__global__ void prep_kernel(const float* __restrict__ x, __half* __restrict__ xh,
                            float* __restrict__ gpart, float* __restrict__ gap2,
                            const float* __restrict__ w1fr, const float* __restrict__ w1fi,
                            float* __restrict__ bank1,
                            const float* __restrict__ w2fr, const float* __restrict__ w2fi,
                            float* __restrict__ bank2) {
    const int bid = blockIdx.x;
    if (bid < 2048) {
        __shared__ __half sm[128 * 130];
        const int b = bid >> 7, gy = bid & 127;
        const int w = threadIdx.x >> 5, l = threadIdx.x & 31;
#pragma unroll 4
        for (int rep = 0; rep < 16; rep++) {
            int ci = w * 16 + rep;
            float4 v = __ldg(reinterpret_cast<const float4*>(
                x + ((size_t)(b * 128 + ci) * HW + gy) * HW) + l);
            float s = (v.x + v.y) + (v.z + v.w);
            for (int o = 16; o; o >>= 1) s += __shfl_down_sync(0xffffffffu, s, o);
            if (l == 0) gpart[((size_t)b * 128 + gy) * 128 + ci] = s;
            __half2 h0 = __floats2half2_rn(v.x, v.y);
            __half2 h1 = __floats2half2_rn(v.z, v.w);
            *reinterpret_cast<__half2*>(&sm[ci * 130 + l * 4])     = h0;
            *reinterpret_cast<__half2*>(&sm[ci * 130 + l * 4 + 2]) = h1;
        }
        __syncthreads();
        const int gx = threadIdx.x >> 1, part = threadIdx.x & 1;
        __half* dst = xh + ((size_t)(b * 128 + gy) * 128 + gx) * 128 + part * 64;
#pragma unroll
        for (int c8 = 0; c8 < 8; c8++) {
            __half h[8];
#pragma unroll
            for (int j = 0; j < 8; j++) h[j] = sm[(part * 64 + c8 * 8 + j) * 130 + gx];
            __half2 p0 = __halves2half2(h[0], h[1]);
            __half2 p1 = __halves2half2(h[2], h[3]);
            __half2 p2 = __halves2half2(h[4], h[5]);
            __half2 p3 = __halves2half2(h[6], h[7]);
            uint4 u;
            u.x = *reinterpret_cast<uint32_t*>(&p0);
            u.y = *reinterpret_cast<uint32_t*>(&p1);
            u.z = *reinterpret_cast<uint32_t*>(&p2);
            u.w = *reinterpret_cast<uint32_t*>(&p3);
            *reinterpret_cast<uint4*>(dst + c8 * 8) = u;
        }
    } else if (bid < 2064) {
        int i = (bid - 2048) * 256 + threadIdx.x;
        if (i < NB * 256) gap2[i] = 0.f;
    } else if (bid < 2576) {
        int idx = (bid - 2064) * 256 + threadIdx.x;
        if (idx < 4 * CO * 128) synth_body(w1fr, w1fi, bank1, 128, idx);
    } else {
        int idx = (bid - 2576) * 256 + threadIdx.x;
        if (idx < 4 * CO * 256) synth_body(w2fr, w2fi, bank2, 256, idx);
    }
}

// ---------------- GAP -> MLP -> softmax (parts: reduce per-gy partials) ----------------
__global__ void attn_kernel(const float* __restrict__ gap, const float* __restrict__ w1,
                            const float* __restrict__ b1, const float* __restrict__ w2,
                            const float* __restrict__ b2, float* __restrict__ attn,
                            int C, int Hd, int parts) {
    __shared__ float gs[256];
    __shared__ float hbuf[64];
    int b = blockIdx.x;
    if (parts) {
        for (int i = threadIdx.x; i < C; i += blockDim.x) {
            float s = 0.f;
            const float* p = gap + (size_t)b * 128 * 128 + i;
            for (int gy = 0; gy < 128; gy++) s += p[gy * 128];
            gs[i] = s * (1.f / (HW * HW));
        }
    } else {
        for (int i = threadIdx.x; i < C; i += blockDim.x) gs[i] = gap[b * C + i];
    }
    __syncthreads();
    for (int j = threadIdx.x; j < Hd; j += blockDim.x) {
        float s = b1[j];
        for (int c = 0; c < C; c++) s += gs[c] * w1[c * Hd + j];
        hbuf[j] = fmaxf(s, 0.f);
    }
    __syncthreads();
    if (threadIdx.x == 0) {
        float l[4];
        float m = -1e30f;
        for (int k = 0; k < 4; k++) {
            float s = b2[k];
            for (int j = 0; j < Hd; j++) s += hbuf[j] * w2[j * 4 + k];
            l[k] = s; m = fmaxf(m, s);
        }
        float sum = 0.f;
        for (int k = 0; k < 4; k++) { l[k] = expf(l[k] - m); sum += l[k]; }
        float inv = 1.f / sum;
        for (int k = 0; k < 4; k++) attn[b * 4 + k] = l[k] * inv;
    }
}

// ---------------- weight mix ----------------
__global__ void mix_kernel(const float* __restrict__ bank, const float* __restrict__ attn,
                           __half* __restrict__ wmix, int K) {
    int total = NB * CO * (K / 2);
    int i = blockIdx.x * blockDim.x + threadIdx.x;
    if (i >= total) return;
    int perb = CO * (K / 2);
    int b = i / perb;
    int r = (i - b * perb) * 2;           // co*K + k  (tap-major k)
    float a0 = attn[b * 4 + 0], a1 = attn[b * 4 + 1];
    float a2 = attn[b * 4 + 2], a3 = attn[b * 4 + 3];
    int plane = CO * K;
    const float* p = bank + r;
    float x0 = a0 * p[0] + a1 * p[plane] + a2 * p[2 * plane] + a3 * p[3 * plane];
    float x1 = a0 * p[1] + a1 * p[plane + 1] + a2 * p[2 * plane + 1] + a3 * p[3 * plane + 1];
    reinterpret_cast<__half2*>(wmix)[i] = __floats2half2_rn(x0, x1);
}

// ---------------- HMMA implicit-GEMM conv (persistent NHWC im2col plane) ----------------
// CTA = (b, 128-co half, 2 rows = 256 px). 512 thr, 16 warps 4x4 (32co x 64px tiles).
// B: per-64ci group, one smem plane [4 gy][130 gx][64 ci] (rows 144B) serves all 9 taps;
// (dy,dx) shift = row-pointer offset, non-trans ldmatrix (px-major B). Double-buffered.
// A: wmix chunks quad-buffered via cp.async, issued per-chunk mid-compute (R14 schedule).
// Synchronization: ONE CP_WAIT(0)+barrier per PAIR of chunks (A fence distance allows it).
#define SA    72                  // halves per A row (144B)
#define ABYTES (128 * SA * 2)     // 18432
#define BROW  144                 // bytes per B plane row (64 ci + pad)
#define SBP   (520 * BROW)        // 74880 bytes per plane (4*130 rows)
#define SBOFF (4 * ABYTES)        // 73728
#define SMTOT (SBOFF + 2 * SBP)   // 223488

template<int CIN, bool OUT_HALF, bool GAP_OUT>
__global__ void __launch_bounds__(512, 1)
conv_hmma_kernel(const __half* __restrict__ xh, const __half* __restrict__ wmix,
                 const float* __restrict__ bias, void* __restrict__ outv,
                 float* __restrict__ gapout) {
    constexpr int K    = CIN * 9;
    constexpr int NCIG = CIN / 64;
    constexpr int NCH  = 9 * NCIG;

    extern __shared__ __align__(16) char smem[];
    const uint32_t sbase = smem_u32(smem);
    const uint32_t sbB   = sbase + SBOFF;

    const int tid = threadIdx.x, wid = tid >> 5, lane = tid & 31;
    const int b   = blockIdx.z;
    const int co0 = blockIdx.y * 128;
    const int y0  = blockIdx.x * 2;
    const int wr = wid & 3, wc = wid >> 2;

    const __half* xb = xh + (size_t)b * HW * HW * CIN;     // NHWC
    const __half* wb = wmix + (size_t)(b * 256 + co0) * K;

    float d[2][8][4];
#pragma unroll
    for (int mt = 0; mt < 2; mt++)
#pragma unroll
        for (int nt = 0; nt < 8; nt++)
#pragma unroll
            for (int q = 0; q < 4; q++) d[mt][nt][q] = 0.f;

    // A cp.async mapping: thread -> rows (tid>>3, +64), seg tid&7
    const int arow = tid >> 3, aseg = tid & 7;
    const __half* asrc0 = wb + (size_t)arow * K + aseg * 8;
    const uint32_t adst0 = sbase + (uint32_t)(arow * SA + aseg * 8) * 2;

    auto cpa_a = [&](int cc) {
        int tap = cc % 9, cig = cc / 9;
        const __half* asrc = asrc0 + tap * CIN + cig * 64;
        const uint32_t adst = adst0 + (cc & 3) * ABYTES;
        cp_async16(adst, asrc);
        cp_async16(adst + 64 * SA * 2, asrc + (size_t)64 * K);
    };

    // fill B plane for ci-group cig into buffer (cig&1): 4096 tasks (4gy x 128gx x 8seg)
    auto fill_b = [&](int cig) {
        const uint32_t pl = sbB + (cig & 1) * SBP;
#pragma unroll
        for (int i = 0; i < 8; i++) {
            int task = tid + i * 512;
            int gy = task >> 10, rem = task & 1023, gx = rem >> 3, seg = rem & 7;
            int gyg = y0 + gy - 1;
            if ((unsigned)gyg < 128u) {
                uint32_t dst = pl + (uint32_t)((gy * 130 + gx + 1) * BROW + seg * 16);
                const __half* src = xb + ((size_t)gyg * HW + gx) * CIN + cig * 64 + seg * 8;
                cp_async16(dst, src);
            }
        }
    };

    // ---- zero halo / OOB rows of both planes ----
    for (int i = tid; i < 2 * 8 * 36; i += 512) {
        int pl = i / 288, r8 = (i / 36) % 8, u = i % 36;
        int gy = r8 >> 1;
        int row = gy * 130 + ((r8 & 1) ? 129 : 0);
        *reinterpret_cast<uint32_t*>(smem + SBOFF + pl * SBP + row * BROW + u * 4) = 0u;
    }
    if (y0 == 0) {
        for (int i = tid; i < 2 * 130 * 36; i += 512) {
            int pl = i / (130 * 36), r = (i / 36) % 130, u = i % 36;
            *reinterpret_cast<uint32_t*>(smem + SBOFF + pl * SBP + r * BROW + u * 4) = 0u;
        }
    }
    if (y0 == 126) {
        for (int i = tid; i < 2 * 130 * 36; i += 512) {
            int pl = i / (130 * 36), r = (i / 36) % 130 + 390, u = i % 36;
            *reinterpret_cast<uint32_t*>(smem + SBOFF + pl * SBP + r * BROW + u * 4) = 0u;
        }
    }
    __syncthreads();

    // ---- prologue: first plane + first two A chunks (fully drained + fenced) ----
    fill_b(0);
    cpa_a(0); CP_COMMIT();
    cpa_a(1); CP_COMMIT();
    CP_WAIT(0);
    __syncthreads();

    // ---- pair loop: R14 per-chunk issue schedule, barrier every 2 chunks ----
    for (int q = 0; q < NCH / 2; q++) {
#pragma unroll
        for (int j = 0; j < 2; j++) {
            const int c = 2 * q + j;
            const int tap = c % 9, cig = c / 9;
            const int dy = tap / 3, dx = tap % 3;
            const uint32_t sa = sbase + (c & 3) * ABYTES;
            const uint32_t bplane = sbB + (cig & 1) * SBP;

            uint32_t brow[4];
#pragma unroll
            for (int ng = 0; ng < 4; ng++) {
                int n_g = wc * 64 + ng * 16 + (lane & 7) + ((lane >> 4) << 3);
                int yr = n_g >> 7, gx = n_g & 127;
                brow[ng] = bplane + (uint32_t)(((yr + dy) * 130 + gx + dx) * BROW
                                               + ((lane >> 3) & 1) * 16);
            }

            auto kstep = [&](int ks) {
                uint32_t a[2][4];
#pragma unroll
                for (int mt = 0; mt < 2; mt++) {
                    uint32_t addr = sa + (uint32_t)((wr * 32 + mt * 16 + (lane & 15)) * SA
                                                    + ks * 16 + (lane >> 4) * 8) * 2;
                    ldsm_x4(a[mt][0], a[mt][1], a[mt][2], a[mt][3], addr);
                }
                uint32_t bf[2][4];
                ldsm_x4(bf[0][0], bf[0][1], bf[0][2], bf[0][3], brow[0] + ks * 32);
#pragma unroll
                for (int ng = 0; ng < 4; ng++) {
                    if (ng < 3)
                        ldsm_x4(bf[(ng + 1) & 1][0], bf[(ng + 1) & 1][1],
                                bf[(ng + 1) & 1][2], bf[(ng + 1) & 1][3],
                                brow[ng + 1] + ks * 32);
                    const uint32_t* f = bf[ng & 1];
#pragma unroll
                    for (int mt = 0; mt < 2; mt++) {
                        mma16816(d[mt][ng * 2 + 0], a[mt], f[0], f[1]);
                        mma16816(d[mt][ng * 2 + 1], a[mt], f[2], f[3]);
                    }
                }
            };

            kstep(0);
            // plane fill spread mid-compute; r==1 guarantees pair-barrier separation
            // from the previous plane's last readers (chunk 9cig-1) and its first
            // consumers (chunk 9(cig+1)) for both pair parities.
            if (tap == 1 && cig + 1 < NCIG) fill_b(cig + 1);
            kstep(1);
            if (c + 2 < NCH) cpa_a(c + 2);
            CP_COMMIT();
            kstep(2);
            kstep(3);
        }
        CP_WAIT(0);            // A(c+2),A(c+3) and any plane fill landed
        __syncthreads();       // fence for all cross-warp smem reads next pair
    }

    // ---- epilogue ----
    if (GAP_OUT) {
#pragma unroll
        for (int mt = 0; mt < 2; mt++) {
#pragma unroll
            for (int h = 0; h < 2; h++) {
                int co = co0 + wr * 32 + mt * 16 + (lane >> 2) + h * 8;
                float bv = bias[co];
                float gs = 0.f;
#pragma unroll
                for (int nt = 0; nt < 8; nt++) {
                    gs += fmaxf(d[mt][nt][h * 2 + 0] + bv, 0.f)
                        + fmaxf(d[mt][nt][h * 2 + 1] + bv, 0.f);
                }
                gs += __shfl_xor_sync(0xffffffffu, gs, 1);
                gs += __shfl_xor_sync(0xffffffffu, gs, 2);
                if ((lane & 3) == 0)
                    atomicAdd(&gapout[b * 256 + co], gs * (1.f / (HW * HW)));
            }
        }
    }

    if (OUT_HALF) {
        // stage [px 256][co 136] fp16 in B smem area, then coalesced NHWC writes
        __half* st = reinterpret_cast<__half*>(smem + SBOFF);
#pragma unroll
        for (int mt = 0; mt < 2; mt++) {
#pragma unroll
            for (int h = 0; h < 2; h++) {
                int col = wr * 32 + mt * 16 + (lane >> 2) + h * 8;
                float bv = bias[co0 + col];
#pragma unroll
                for (int nt = 0; nt < 8; nt++) {
                    int px = wc * 64 + nt * 8 + (lane & 3) * 2;
                    st[px * 136 + col]       = __float2half(fmaxf(d[mt][nt][h * 2 + 0] + bv, 0.f));
                    st[(px + 1) * 136 + col] = __float2half(fmaxf(d[mt][nt][h * 2 + 1] + bv, 0.f));
                }
            }
        }
        __syncthreads();
        const int px = tid >> 1, part = tid & 1;
        int gyO = y0 + (px >> 7), gx = px & 127;
        __half* dst = (__half*)outv + ((size_t)(b * 128 + gyO) * 128 + gx) * 256 + co0 + part * 64;
#pragma unroll
        for (int c8 = 0; c8 < 8; c8++) {
            __half h[8];
#pragma unroll
            for (int j = 0; j < 8; j++) h[j] = st[px * 136 + part * 64 + c8 * 8 + j];
            __half2 p0 = __halves2half2(h[0], h[1]);
            __half2 p1 = __halves2half2(h[2], h[3]);
            __half2 p2 = __halves2half2(h[4], h[5]);
            __half2 p3 = __halves2half2(h[6], h[7]);
            uint4 u;
            u.x = *reinterpret_cast<uint32_t*>(&p0);
            u.y = *reinterpret_cast<uint32_t*>(&p1);
            u.z = *reinterpret_cast<uint32_t*>(&p2);
            u.w = *reinterpret_cast<uint32_t*>(&p3);
            *reinterpret_cast<uint4*>(dst + c8 * 8) = u;
        }
    } else {
        // NCHW fp32 direct stores (final output)
#pragma unroll
        for (int mt = 0; mt < 2; mt++) {
#pragma unroll
            for (int h = 0; h < 2; h++) {
                int co = co0 + wr * 32 + mt * 16 + (lane >> 2) + h * 8;
                float bv = bias[co];
                size_t base = ((size_t)(b * 256 + co) * HW + y0) * HW;
#pragma unroll
                for (int nt = 0; nt < 8; nt++) {
                    int px = wc * 64 + nt * 8 + (lane & 3) * 2;
                    int yr = px >> 7, xx = px & 127;
                    float2 fv;
                    fv.x = fmaxf(d[mt][nt][h * 2 + 0] + bv, 0.f);
                    fv.y = fmaxf(d[mt][nt][h * 2 + 1] + bv, 0.f);
                    *reinterpret_cast<float2*>((float*)outv + base + yr * HW + xx) = fv;
                }
            }
        }
    }
}

// ---------------- launch ----------------
extern "C" void kernel_launch(void* const* d_in, const int* in_sizes, int n_in,
                              void* d_out, int out_size) {
    const float* x    = (const float*)d_in[0];
    const float* w1fr = (const float*)d_in[1];
    const float* w1fi = (const float*)d_in[2];
    const float* b1   = (const float*)d_in[3];
    const float* a1w1 = (const float*)d_in[4];
    const float* a1b1 = (const float*)d_in[5];
    const float* a1w2 = (const float*)d_in[6];
    const float* a1b2 = (const float*)d_in[7];
    const float* w2fr = (const float*)d_in[8];
    const float* w2fi = (const float*)d_in[9];
    const float* b2   = (const float*)d_in[10];
    const float* a2w1 = (const float*)d_in[11];
    const float* a2b1 = (const float*)d_in[12];
    const float* a2w2 = (const float*)d_in[13];
    const float* a2b2 = (const float*)d_in[14];
    float* out = (float*)d_out;

    float *bank1, *bank2, *gpart, *gap2, *attnb;
    __half *wm1, *wm2, *xhb, *yhb;
    cudaGetSymbolAddress((void**)&bank1, g_bank1);
    cudaGetSymbolAddress((void**)&bank2, g_bank2);
    cudaGetSymbolAddress((void**)&gpart, g_gpart);
    cudaGetSymbolAddress((void**)&gap2,  g_gap2);
    cudaGetSymbolAddress((void**)&attnb, g_attn);
    cudaGetSymbolAddress((void**)&wm1,   g_wmix1);
    cudaGetSymbolAddress((void**)&wm2,   g_wmix2);
    cudaGetSymbolAddress((void**)&xhb,   g_xh);
    cudaGetSymbolAddress((void**)&yhb,   g_yh);

    cudaFuncSetAttribute(conv_hmma_kernel<128, true, true>,
                         cudaFuncAttributeMaxDynamicSharedMemorySize, SMTOT);
    cudaFuncSetAttribute(conv_hmma_kernel<256, false, false>,
                         cudaFuncAttributeMaxDynamicSharedMemorySize, SMTOT);

    // Launch order: conv1 is launch index 3 (the one ncu captures).
    prep_kernel<<<3600, 256>>>(x, xhb, gpart, gap2,
                               w1fr, w1fi, bank1, w2fr, w2fi, bank2);                 // 0
    attn_kernel<<<NB, 128>>>(gpart, a1w1, a1b1, a1w2, a1b2, attnb, 128, 32, 1);       // 1
    {
        int K = 128 * 9;
        int total = NB * CO * (K / 2);
        mix_kernel<<<(total + 255) / 256, 256>>>(bank1, attnb, wm1, K);               // 2
    }
    conv_hmma_kernel<128, true, true><<<dim3(64, 2, NB), 512, SMTOT>>>(xhb, wm1, b1, yhb, gap2);  // 3

    attn_kernel<<<NB, 128>>>(gap2, a2w1, a2b1, a2w2, a2b2, attnb, 256, 64, 0);        // 4
    {
        int K = 256 * 9;
        int total = NB * CO * (K / 2);
        mix_kernel<<<(total + 255) / 256, 256>>>(bank2, attnb, wm2, K);               // 5
    }
    conv_hmma_kernel<256, false, false><<<dim3(64, 2, NB), 512, SMTOT>>>(yhb, wm2, b2, out, nullptr);  // 6
}